// round 2
// baseline (speedup 1.0000x reference)
#include <cuda_runtime.h>
#include <cuda_bf16.h>

// FocalLoss: input [N,C]=[1048576,80] fp32, target [N] int32 (JAX x64 off), gamma=2.
// out[0] = mean_n sum_c -(1-pt)^2 * logpt,  logpt = log_sigmoid(sign*x)
//
// Two launches: main grid computes per-block double partials (deterministic),
// finalize block reduces partials and writes the fp32 mean.

#define N_ROWS   1048576
#define C_CLS    80
#define C4       (C_CLS / 4)           // 20 float4 per row
#define NBLOCKS  1184                  // 148 SMs * 8
#define NTHREADS 256

__device__ double g_partials[NBLOCKS];

__device__ __forceinline__ float focal_elem(float v, bool is_target) {
    float x  = is_target ? v : -v;
    float ax = fabsf(x);
    float e  = __expf(-ax);                    // exp(-|x|) in (0,1]
    float logpt = fminf(x, 0.0f) - __logf(1.0f + e);  // log_sigmoid(x), stable
    float pt = __expf(logpt);                  // sigmoid(x)
    float omp = 1.0f - pt;
    return -(omp * omp) * logpt;               // positive
}

__global__ __launch_bounds__(NTHREADS) void focal_main_kernel(
    const float* __restrict__ inp,
    const int* __restrict__ tgt)
{
    const unsigned n4 = (unsigned)N_ROWS * C4;      // 20,971,520
    const unsigned stride = gridDim.x * blockDim.x;
    unsigned i = blockIdx.x * blockDim.x + threadIdx.x;

    float fsum = 0.0f;
    const float4* __restrict__ inp4 = (const float4*)inp;

    for (; i < n4; i += stride) {
        unsigned row  = i / (unsigned)C4;           // mul-by-magic, cheap
        unsigned col0 = (i - row * (unsigned)C4) * 4u;
        int t = __ldg(&tgt[row]);
        float4 v = __ldg(&inp4[i]);

        fsum += focal_elem(v.x, (int)col0     == t);
        fsum += focal_elem(v.y, (int)col0 + 1 == t);
        fsum += focal_elem(v.z, (int)col0 + 2 == t);
        fsum += focal_elem(v.w, (int)col0 + 3 == t);
    }

    // warp reduce (float), then block reduce in double
    #pragma unroll
    for (int off = 16; off > 0; off >>= 1)
        fsum += __shfl_down_sync(0xFFFFFFFFu, fsum, off);

    __shared__ double s_warp[NTHREADS / 32];
    int lane = threadIdx.x & 31;
    int wid  = threadIdx.x >> 5;
    if (lane == 0) s_warp[wid] = (double)fsum;
    __syncthreads();

    if (threadIdx.x == 0) {
        double bsum = 0.0;
        #pragma unroll
        for (int w = 0; w < NTHREADS / 32; w++) bsum += s_warp[w];
        g_partials[blockIdx.x] = bsum;
    }
}

__global__ __launch_bounds__(1024) void focal_finalize_kernel(float* __restrict__ out)
{
    __shared__ double s[1024];
    double v = 0.0;
    for (int i = threadIdx.x; i < NBLOCKS; i += 1024)
        v += g_partials[i];
    s[threadIdx.x] = v;
    __syncthreads();
    for (int off = 512; off > 0; off >>= 1) {
        if (threadIdx.x < off) s[threadIdx.x] += s[threadIdx.x + off];
        __syncthreads();
    }
    if (threadIdx.x == 0)
        out[0] = (float)(s[0] / (double)N_ROWS);
}

extern "C" void kernel_launch(void* const* d_in, const int* in_sizes, int n_in,
                              void* d_out, int out_size)
{
    const float* inp = (const float*)d_in[0];
    const int* tgt   = (const int*)d_in[1];
    float* out       = (float*)d_out;

    focal_main_kernel<<<NBLOCKS, NTHREADS>>>(inp, tgt);
    focal_finalize_kernel<<<1, 1024>>>(out);
}